// round 14
// baseline (speedup 1.0000x reference)
#include <cuda_runtime.h>
#include <cuda_bf16.h>
#include <mma.h>
#include <math.h>

using namespace nvcuda;

#define NU 100000
#define NR 50000
#define NE 600000
#define NL 200000
#define HD 128
#define OD 64
#define NUH 50000   // u-side pipeline split point

// ---------------- scratch (direct-store targets padded to tile multiple) ----------------
__device__ __align__(16) float g_hu[(size_t)NU * HD];
__device__ __align__(16) float g_hr[(size_t)NR * HD];
__device__ __align__(16) float g_p1[(size_t)(NR + 64) * HD];
__device__ __align__(16) float g_u1[(size_t)NU * HD];
__device__ __align__(16) float g_r1[(size_t)NR * HD];
__device__ __align__(16) float g_mean_u[(size_t)(NU + 64) * HD]; // mu, then U2
__device__ __align__(16) float g_mean_r[(size_t)(NR + 64) * HD]; // mr, then R2
__device__ __align__(16) float g_zu[(size_t)NU * OD];
__device__ __align__(16) float g_zr[(size_t)NR * OD];

// bf16 split weights, padded row pitches per matrix
__device__ __align__(16) __nv_bfloat16 g_wbh[154624];
__device__ __align__(16) __nv_bfloat16 g_wbl[154624];
#define WB_WU      0        // Wu        [128][136]
#define WB_WREC    17408    // Wrec      [128][264]
#define WB_P1      51200    // c1_ru_Wl  [128][136]
#define WB_C1UR    68608    // [c1_ur_Wl | c1_ur_Wr] stacked-K [128][264]
#define WB_C1RUWR  102400   // c1_ru_Wr  [128][136]
#define WB_U2      119808   // rows 0-63 c2_ur_Wl, 64-127 c2_ru_Wr  [128][136]
#define WB_R2      137216   // rows 0-63 c2_ru_Wl, 64-127 c2_ur_Wr  [128][136]

__device__ int g_deg_r[NR];
__device__ int g_deg_u[NU];
__device__ int g_off_r[NR + 1];
__device__ int g_off_u[NU + 1];
__device__ int g_cur_r[NR];
__device__ int g_cur_u[NU];
__device__ int g_csr_r[NE];
__device__ int g_csr_u[NE];

// ---------------- CSR build ----------------
__global__ void zero_deg(int* __restrict__ deg_u, int* __restrict__ deg_r)
{
    int t = blockIdx.x * blockDim.x + threadIdx.x;
    if (t < NU) deg_u[t] = 0;
    if (t < NR) deg_r[t] = 0;
}

__global__ void count_kernel(const int* __restrict__ es, const int* __restrict__ ed,
                             int* __restrict__ deg_u, int* __restrict__ deg_r, int E)
{
    int t = blockIdx.x * blockDim.x + threadIdx.x;
    if (t < E) {
        atomicAdd(&deg_u[es[t]], 1);
        atomicAdd(&deg_r[ed[t]], 1);
    }
}

__global__ void scan2_kernel(const int* __restrict__ deg_r, int* __restrict__ off_r,
                             int* __restrict__ cur_r,
                             const int* __restrict__ deg_u, int* __restrict__ off_u,
                             int* __restrict__ cur_u)
{
    const int* deg; int* off; int* cur; int n;
    if (blockIdx.x == 0) { deg = deg_r; off = off_r; cur = cur_r; n = NR; }
    else                 { deg = deg_u; off = off_u; cur = cur_u; n = NU; }
    __shared__ int tmp[1024];
    int t = threadIdx.x;
    int chunk = (n + 1023) / 1024;
    int start = min(t * chunk, n);
    int end = min(start + chunk, n);
    int s = 0;
    for (int i = start; i < end; i++) s += deg[i];
    tmp[t] = s;
    __syncthreads();
    for (int d = 1; d < 1024; d <<= 1) {
        int v = (t >= d) ? tmp[t - d] : 0;
        __syncthreads();
        tmp[t] += v;
        __syncthreads();
    }
    int run = (t == 0) ? 0 : tmp[t - 1];
    for (int i = start; i < end; i++) {
        off[i] = run;
        cur[i] = run;
        run += deg[i];
    }
    if (end == n) off[n] = run;
}

__global__ void fill_kernel(const int* __restrict__ es, const int* __restrict__ ed,
                            int* __restrict__ cur_u, int* __restrict__ cur_r,
                            int* __restrict__ csr_u, int* __restrict__ csr_r, int E)
{
    int t = blockIdx.x * blockDim.x + threadIdx.x;
    if (t < E) {
        int s = es[t], d = ed[t];
        int pr = atomicAdd(&cur_r[d], 1);
        csr_r[pr] = s;
        int pu = atomicAdd(&cur_u[s], 1);
        csr_u[pu] = d;
    }
}

// ---------------- bf16 split weight prep ----------------
struct WcArgs {
    const float* src[10];
    int nrows[10];
    int kcols[10];
    int cover[10];
    int pitch[10];
    int base[10];
    int blk_off[11];
};

__global__ void wconv_kernel(WcArgs a, __nv_bfloat16* __restrict__ hi,
                             __nv_bfloat16* __restrict__ lo)
{
    int b = blockIdx.x;
    int m = 0;
    while (b >= a.blk_off[m + 1]) m++;
    int idx = (b - a.blk_off[m]) * 256 + threadIdx.x;
    int NR_ = a.nrows[m], KC = a.kcols[m], CV = a.cover[m];
    if (idx < NR_ * CV) {
        int r = idx / CV, c = idx - r * CV;
        float v = (c < KC) ? a.src[m][r * KC + c] : 0.f;
        __nv_bfloat16 h = __float2bfloat16(v);
        float rr = v - __bfloat162float(h);
        int d = a.base[m] + r * a.pitch[m] + c;
        hi[d] = h;
        lo[d] = __float2bfloat16(rr);
    }
}

// ---------------- wmma split-bf16 GEMM ----------------
// DIRECT: no epilogue — store accumulators straight to gmem (Y padded to 64-row mult).
template <int K, bool DUAL, bool ADDIN, bool HASB, bool RELU, bool DIRECT>
__global__ __launch_bounds__(256) void gemm_wmma(
    const float* __restrict__ A, const float* __restrict__ X,
    const __nv_bfloat16* __restrict__ Whi, const __nv_bfloat16* __restrict__ Wlo,
    const float* __restrict__ bl, const float* __restrict__ ADDP,
    float* __restrict__ Y, int M)
{
    constexpr int KP = K + 8;
    constexpr int QR = K / 4;
    extern __shared__ __nv_bfloat16 smemb[];
    __nv_bfloat16* sWhi = smemb;
    __nv_bfloat16* sWlo = sWhi + 128 * KP;
    __nv_bfloat16* sAhi = sWlo + 128 * KP;
    __nv_bfloat16* sAlo = sAhi + 64 * KP;
    float* sOut = (float*)sAhi;

    const int tid = threadIdx.x;

    {
        const uint4* src = (const uint4*)Whi;
        uint4* dst = (uint4*)sWhi;
        for (int i = tid; i < 128 * KP / 8; i += 256) dst[i] = src[i];
        const uint4* src2 = (const uint4*)Wlo;
        uint4* dst2 = (uint4*)sWlo;
        for (int i = tid; i < 128 * KP / 8; i += 256) dst2[i] = src2[i];
    }

    const int w = tid >> 5;
    const int mrow0 = (w >> 2) * 32;
    const int ncol0 = (w & 3) * 32;

    const int ntiles = (M + 63) >> 6;
    for (int tile = blockIdx.x; tile < ntiles; tile += gridDim.x) {
        const int row0 = tile << 6;
        __syncthreads();
        {
            int rows = min(64, M - row0);
            for (int i = tid; i < 64 * QR; i += 256) {
                int r = i / QR, q = i - r * QR;
                float4 v = make_float4(0.f, 0.f, 0.f, 0.f);
                if (r < rows) {
                    if (DUAL) {
                        v = (q < 32)
                          ? *(const float4*)(A + (size_t)(row0 + r) * 128 + 4 * q)
                          : *(const float4*)(X + (size_t)(row0 + r) * 128 + 4 * (q - 32));
                    } else {
                        v = *(const float4*)(A + (size_t)(row0 + r) * K + 4 * q);
                    }
                }
                float vv[4] = {v.x, v.y, v.z, v.w};
                unsigned ph0 = 0, ph1 = 0, pl0 = 0, pl1 = 0;
#pragma unroll
                for (int qq = 0; qq < 2; qq++) {
                    __nv_bfloat16 h = __float2bfloat16(vv[qq]);
                    __nv_bfloat16 l = __float2bfloat16(vv[qq] - __bfloat162float(h));
                    ph0 |= (unsigned)__bfloat16_as_ushort(h) << (16 * qq);
                    pl0 |= (unsigned)__bfloat16_as_ushort(l) << (16 * qq);
                }
#pragma unroll
                for (int qq = 0; qq < 2; qq++) {
                    __nv_bfloat16 h = __float2bfloat16(vv[2 + qq]);
                    __nv_bfloat16 l = __float2bfloat16(vv[2 + qq] - __bfloat162float(h));
                    ph1 |= (unsigned)__bfloat16_as_ushort(h) << (16 * qq);
                    pl1 |= (unsigned)__bfloat16_as_ushort(l) << (16 * qq);
                }
                *(uint2*)&sAhi[r * KP + 4 * q] = make_uint2(ph0, ph1);
                *(uint2*)&sAlo[r * KP + 4 * q] = make_uint2(pl0, pl1);
            }
        }
        __syncthreads();

        wmma::fragment<wmma::accumulator, 16, 16, 16, float> acc[2][2];
#pragma unroll
        for (int i = 0; i < 2; i++)
#pragma unroll
            for (int j = 0; j < 2; j++) wmma::fill_fragment(acc[i][j], 0.f);

        for (int k0 = 0; k0 < K; k0 += 16) {
            wmma::fragment<wmma::matrix_a, 16, 16, 16, __nv_bfloat16, wmma::row_major> ahi[2], alo[2];
            wmma::fragment<wmma::matrix_b, 16, 16, 16, __nv_bfloat16, wmma::col_major> bhi[2], blo[2];
#pragma unroll
            for (int i = 0; i < 2; i++) {
                wmma::load_matrix_sync(ahi[i], sAhi + (mrow0 + 16 * i) * KP + k0, KP);
                wmma::load_matrix_sync(alo[i], sAlo + (mrow0 + 16 * i) * KP + k0, KP);
            }
#pragma unroll
            for (int j = 0; j < 2; j++) {
                wmma::load_matrix_sync(bhi[j], sWhi + (ncol0 + 16 * j) * KP + k0, KP);
                wmma::load_matrix_sync(blo[j], sWlo + (ncol0 + 16 * j) * KP + k0, KP);
            }
#pragma unroll
            for (int i = 0; i < 2; i++)
#pragma unroll
                for (int j = 0; j < 2; j++) {
                    wmma::mma_sync(acc[i][j], ahi[i], bhi[j], acc[i][j]);
                    wmma::mma_sync(acc[i][j], ahi[i], blo[j], acc[i][j]);
                    wmma::mma_sync(acc[i][j], alo[i], bhi[j], acc[i][j]);
                }
        }

        if (DIRECT) {
#pragma unroll
            for (int i = 0; i < 2; i++)
#pragma unroll
                for (int j = 0; j < 2; j++)
                    wmma::store_matrix_sync(
                        Y + (size_t)(row0 + mrow0 + 16 * i) * 128 + ncol0 + 16 * j,
                        acc[i][j], 128, wmma::mem_row_major);
        } else {
            __syncthreads();
#pragma unroll
            for (int i = 0; i < 2; i++)
#pragma unroll
                for (int j = 0; j < 2; j++)
                    wmma::store_matrix_sync(sOut + (mrow0 + 16 * i) * 128 + ncol0 + 16 * j,
                                            acc[i][j], 128, wmma::mem_row_major);
            __syncthreads();

            int rows = min(64, M - row0);
            for (int i = tid; i < 64 * 32; i += 256) {
                int r = i >> 5, c4 = i & 31;
                if (r < rows) {
                    float4 v = ((const float4*)sOut)[i];
                    if (HASB) {
                        float4 b4 = *(const float4*)(bl + 4 * c4);
                        v.x += b4.x; v.y += b4.y; v.z += b4.z; v.w += b4.w;
                    }
                    if (ADDIN) {
                        float4 a4 = *(const float4*)(ADDP + (size_t)(row0 + r) * 128 + 4 * c4);
                        v.x += a4.x; v.y += a4.y; v.z += a4.z; v.w += a4.w;
                    }
                    if (RELU) {
                        v.x = fmaxf(v.x, 0.f); v.y = fmaxf(v.y, 0.f);
                        v.z = fmaxf(v.z, 0.f); v.w = fmaxf(v.w, 0.f);
                    }
                    *(float4*)(Y + (size_t)(row0 + r) * 128 + 4 * c4) = v;
                }
            }
        }
    }
}

// ---------------- single-direction gather-mean 128-dim ----------------
__global__ __launch_bounds__(256) void gather_128(
    const float4* __restrict__ feat, const int* __restrict__ off,
    const int* __restrict__ csr, float4* __restrict__ outm, int n)
{
    int warp = (blockIdx.x * blockDim.x + threadIdx.x) >> 5;
    int lane = threadIdx.x & 31;
    if (warp >= n) return;
    int b = off[warp], e = off[warp + 1];
    float4 acc = make_float4(0.f, 0.f, 0.f, 0.f);
    int i = b;
    for (; i + 4 <= e; i += 4) {
        int n0 = csr[i], n1 = csr[i + 1], n2 = csr[i + 2], n3 = csr[i + 3];
        float4 v0 = feat[(size_t)n0 * 32 + lane];
        float4 v1 = feat[(size_t)n1 * 32 + lane];
        float4 v2 = feat[(size_t)n2 * 32 + lane];
        float4 v3 = feat[(size_t)n3 * 32 + lane];
        acc.x += v0.x + v1.x + v2.x + v3.x;
        acc.y += v0.y + v1.y + v2.y + v3.y;
        acc.z += v0.z + v1.z + v2.z + v3.z;
        acc.w += v0.w + v1.w + v2.w + v3.w;
    }
    for (; i < e; i++) {
        int nb = csr[i];
        float4 v = feat[(size_t)nb * 32 + lane];
        acc.x += v.x; acc.y += v.y; acc.z += v.z; acc.w += v.w;
    }
    float inv = 1.f / fmaxf((float)(e - b), 1.f);
    acc.x *= inv; acc.y *= inv; acc.z *= inv; acc.w *= inv;
    outm[(size_t)warp * 32 + lane] = acc;
}

// ---------------- fused 64-dim gather + bias + root + NORMALIZE ----------------
__global__ __launch_bounds__(256) void gather2_64f(
    const float2* __restrict__ U2, const float2* __restrict__ R2,
    const float* __restrict__ bl_ur, const float* __restrict__ bl_ru,
    const int* __restrict__ off_r, const int* __restrict__ csr_r,
    const int* __restrict__ off_u, const int* __restrict__ csr_u,
    float2* __restrict__ zr, float2* __restrict__ zu)
{
    int warp = (blockIdx.x * blockDim.x + threadIdx.x) >> 5;
    int lane = threadIdx.x & 31;
    const float2* feat;
    const float2* selfp;
    const float2* bl;
    const int* off;
    const int* csr;
    float2* outp;
    int node;
    if (warp < NR) {
        node = warp;
        feat = U2; selfp = R2; bl = (const float2*)bl_ur;
        off = off_r; csr = csr_r; outp = zr;
    } else if (warp < NR + NU) {
        node = warp - NR;
        feat = R2; selfp = U2; bl = (const float2*)bl_ru;
        off = off_u; csr = csr_u; outp = zu;
    } else return;
    int b = off[node], e = off[node + 1];
    float2 acc = make_float2(0.f, 0.f);
    int i = b;
    for (; i + 4 <= e; i += 4) {
        int n0 = csr[i], n1 = csr[i + 1], n2 = csr[i + 2], n3 = csr[i + 3];
        float2 v0 = feat[(size_t)n0 * 64 + lane];
        float2 v1 = feat[(size_t)n1 * 64 + lane];
        float2 v2 = feat[(size_t)n2 * 64 + lane];
        float2 v3 = feat[(size_t)n3 * 64 + lane];
        acc.x += v0.x + v1.x + v2.x + v3.x;
        acc.y += v0.y + v1.y + v2.y + v3.y;
    }
    for (; i < e; i++) {
        int nb = csr[i];
        float2 v = feat[(size_t)nb * 64 + lane];
        acc.x += v.x; acc.y += v.y;
    }
    float inv = 1.f / fmaxf((float)(e - b), 1.f);
    float2 s = selfp[(size_t)node * 64 + 32 + lane];
    float2 bb = bl[lane];
    float2 o;
    o.x = acc.x * inv + bb.x + s.x;
    o.y = acc.y * inv + bb.y + s.y;
    float nsum = o.x * o.x + o.y * o.y;
#pragma unroll
    for (int ofs = 16; ofs; ofs >>= 1)
        nsum += __shfl_xor_sync(0xffffffffu, nsum, ofs);
    float innorm = 1.f / fmaxf(sqrtf(nsum), 1e-12f);
    o.x *= innorm; o.y *= innorm;
    outp[(size_t)node * 32 + lane] = o;
}

// ---------------- decoder: dot of pre-normalized rows ----------------
__global__ __launch_bounds__(256) void decode_kernel(
    const float2* __restrict__ zu, const float2* __restrict__ zr,
    const int* __restrict__ ls, const int* __restrict__ ld,
    float* __restrict__ out, int L)
{
    int warp = (blockIdx.x * blockDim.x + threadIdx.x) >> 5;
    int lane = threadIdx.x & 31;
    if (warp >= L) return;
    int s = ls[warp], d = ld[warp];
    float2 a = zu[(size_t)s * 32 + lane];
    float2 b = zr[(size_t)d * 32 + lane];
    float dot = a.x * b.x + a.y * b.y;
#pragma unroll
    for (int o = 16; o; o >>= 1)
        dot += __shfl_xor_sync(0xffffffffu, dot, o);
    if (lane == 0)
        out[warp] = dot;
}

// ---------------- host launch ----------------
extern "C" void kernel_launch(void* const* d_in, const int* in_sizes, int n_in,
                              void* d_out, int out_size)
{
    const float* x_user   = (const float*)d_in[0];
    const float* x_recipe = (const float*)d_in[1];
    const int* edge_src   = (const int*)d_in[2];
    const int* edge_dst   = (const int*)d_in[3];
    const int* lbl_src    = (const int*)d_in[4];
    const int* lbl_dst    = (const int*)d_in[5];
    const float* Wu   = (const float*)d_in[6];
    const float* bu   = (const float*)d_in[7];
    const float* Wrec = (const float*)d_in[8];
    const float* brec = (const float*)d_in[9];
    const float* c1_ur_Wl = (const float*)d_in[10];
    const float* c1_ur_bl = (const float*)d_in[11];
    const float* c1_ur_Wr = (const float*)d_in[12];
    const float* c1_ru_Wl = (const float*)d_in[13];
    const float* c1_ru_bl = (const float*)d_in[14];
    const float* c1_ru_Wr = (const float*)d_in[15];
    const float* c2_ur_Wl = (const float*)d_in[16];
    const float* c2_ur_bl = (const float*)d_in[17];
    const float* c2_ur_Wr = (const float*)d_in[18];
    const float* c2_ru_Wl = (const float*)d_in[19];
    const float* c2_ru_bl = (const float*)d_in[20];
    const float* c2_ru_Wr = (const float*)d_in[21];
    float* out = (float*)d_out;

    float *hu, *hr, *p1, *u1, *r1, *mu, *mr, *zu, *zr;
    __nv_bfloat16 *wbh, *wbl;
    int *deg_r, *deg_u, *off_r, *off_u, *cur_r, *cur_u, *csr_r, *csr_u;
    cudaGetSymbolAddress((void**)&hu, g_hu);
    cudaGetSymbolAddress((void**)&hr, g_hr);
    cudaGetSymbolAddress((void**)&p1, g_p1);
    cudaGetSymbolAddress((void**)&u1, g_u1);
    cudaGetSymbolAddress((void**)&r1, g_r1);
    cudaGetSymbolAddress((void**)&mu, g_mean_u);
    cudaGetSymbolAddress((void**)&mr, g_mean_r);
    cudaGetSymbolAddress((void**)&zu, g_zu);
    cudaGetSymbolAddress((void**)&zr, g_zr);
    cudaGetSymbolAddress((void**)&wbh, g_wbh);
    cudaGetSymbolAddress((void**)&wbl, g_wbl);
    cudaGetSymbolAddress((void**)&deg_r, g_deg_r);
    cudaGetSymbolAddress((void**)&deg_u, g_deg_u);
    cudaGetSymbolAddress((void**)&off_r, g_off_r);
    cudaGetSymbolAddress((void**)&off_u, g_off_u);
    cudaGetSymbolAddress((void**)&cur_r, g_cur_r);
    cudaGetSymbolAddress((void**)&cur_u, g_cur_u);
    cudaGetSymbolAddress((void**)&csr_r, g_csr_r);
    cudaGetSymbolAddress((void**)&csr_u, g_csr_u);

    static cudaStream_t side = nullptr, s2 = nullptr, s3 = nullptr;
    static cudaEvent_t evF = nullptr, evJ = nullptr, evHU = nullptr,
                       evHR = nullptr, evA = nullptr, evP1 = nullptr,
                       evG2 = nullptr;
    if (side == nullptr) {
        cudaStreamCreateWithFlags(&side, cudaStreamNonBlocking);
        cudaStreamCreateWithFlags(&s2, cudaStreamNonBlocking);
        cudaStreamCreateWithFlags(&s3, cudaStreamNonBlocking);
        cudaEventCreateWithFlags(&evF, cudaEventDisableTiming);
        cudaEventCreateWithFlags(&evJ, cudaEventDisableTiming);
        cudaEventCreateWithFlags(&evHU, cudaEventDisableTiming);
        cudaEventCreateWithFlags(&evHR, cudaEventDisableTiming);
        cudaEventCreateWithFlags(&evA, cudaEventDisableTiming);
        cudaEventCreateWithFlags(&evP1, cudaEventDisableTiming);
        cudaEventCreateWithFlags(&evG2, cudaEventDisableTiming);
    }

    const int S_W128 = (2 * 128 * 136 + 2 * 64 * 136) * 2;   // 104448
    const int S_W256 = (2 * 128 * 264 + 2 * 64 * 264) * 2;   // 202752

    cudaFuncSetAttribute((gemm_wmma<128, false, false, true,  false, false>),
                         cudaFuncAttributeMaxDynamicSharedMemorySize, S_W128);
    cudaFuncSetAttribute((gemm_wmma<256, false, false, true,  false, false>),
                         cudaFuncAttributeMaxDynamicSharedMemorySize, S_W256);
    cudaFuncSetAttribute((gemm_wmma<128, false, false, false, false, true>),
                         cudaFuncAttributeMaxDynamicSharedMemorySize, S_W128);
    cudaFuncSetAttribute((gemm_wmma<256, true,  false, true,  true,  false>),
                         cudaFuncAttributeMaxDynamicSharedMemorySize, S_W256);
    cudaFuncSetAttribute((gemm_wmma<128, false, true,  true,  true,  false>),
                         cudaFuncAttributeMaxDynamicSharedMemorySize, S_W128);

    // ---- fork: CSR on side stream ----
    cudaEventRecord(evF, 0);
    cudaStreamWaitEvent(side, evF, 0);
    zero_deg<<<(NU + 255) / 256, 256, 0, side>>>(deg_u, deg_r);
    count_kernel<<<(NE + 255) / 256, 256, 0, side>>>(edge_src, edge_dst, deg_u, deg_r, NE);
    scan2_kernel<<<2, 1024, 0, side>>>(deg_r, off_r, cur_r, deg_u, off_u, cur_u);
    fill_kernel<<<(NE + 255) / 256, 256, 0, side>>>(edge_src, edge_dst, cur_u, cur_r,
                                                    csr_u, csr_r, NE);
    cudaEventRecord(evJ, side);

    // ---- main: bf16 split weight prep ----
    {
        WcArgs a;
        const float* srcs[10] = {Wu, Wrec, c1_ru_Wl,
                                 c1_ur_Wl, c1_ur_Wr,
                                 c1_ru_Wr,
                                 c2_ur_Wl, c2_ru_Wr,
                                 c2_ru_Wl, c2_ur_Wr};
        int nr[10] = {128, 128, 128, 128, 128, 128, 64, 64, 64, 64};
        int kc[10] = {128, 256, 128, 128, 128, 128, 128, 128, 128, 128};
        int cv[10] = {136, 264, 136, 128, 136, 136, 136, 136, 136, 136};
        int pt[10] = {136, 264, 136, 264, 264, 136, 136, 136, 136, 136};
        int bs[10] = {WB_WU, WB_WREC, WB_P1,
                      WB_C1UR, WB_C1UR + 128,
                      WB_C1RUWR,
                      WB_U2, WB_U2 + 64 * 136,
                      WB_R2, WB_R2 + 64 * 136};
        int boff = 0;
        for (int m = 0; m < 10; m++) {
            a.src[m] = srcs[m]; a.nrows[m] = nr[m]; a.kcols[m] = kc[m];
            a.cover[m] = cv[m]; a.pitch[m] = pt[m]; a.base[m] = bs[m];
            a.blk_off[m] = boff;
            boff += (nr[m] * cv[m] + 255) / 256;
        }
        a.blk_off[10] = boff;
        wconv_kernel<<<boff, 256>>>(a, wbh, wbl);
    }

    const int GWR  = (NR * 32 + 255) / 256;
    const int GWUH = (NUH * 32 + 255) / 256;
    const int GW2  = ((NR + NU) * 32 + 255) / 256;

    // ---- main: hu projection; then hr -> p1 ----
    gemm_wmma<128, false, false, true, false, false><<<296, 256, S_W128>>>(
        x_user, nullptr, wbh + WB_WU, wbl + WB_WU, bu, nullptr, hu, NU);
    cudaEventRecord(evHU, 0);

    // ---- s2: gatherR (mr from hu) overlaps hr/p1 GEMMs on main ----
    cudaStreamWaitEvent(s2, evJ, 0);
    cudaStreamWaitEvent(s2, evHU, 0);
    gather_128<<<GWR, 256, 0, s2>>>((const float4*)hu, off_r, csr_r, (float4*)mr, NR);

    gemm_wmma<256, false, false, true, false, false><<<148, 256, S_W256>>>(
        x_recipe, nullptr, wbh + WB_WREC, wbl + WB_WREC, brec, nullptr, hr, NR);
    cudaEventRecord(evHR, 0);
    gemm_wmma<128, false, false, false, false, true><<<296, 256, S_W128>>>(
        hr, nullptr, wbh + WB_P1, wbl + WB_P1, nullptr, nullptr, p1, NR);
    cudaEventRecord(evP1, 0);

    // ---- s2: chain A: r1 (stacked dual) -> R2 ----
    cudaStreamWaitEvent(s2, evHR, 0);
    gemm_wmma<256, true, false, true, true, false><<<148, 256, S_W256, s2>>>(
        mr, hr, wbh + WB_C1UR, wbl + WB_C1UR, c1_ur_bl, nullptr, r1, NR);
    gemm_wmma<128, false, false, false, false, true><<<296, 256, S_W128, s2>>>(
        r1, nullptr, wbh + WB_R2, wbl + WB_R2, nullptr, nullptr, mr, NR);
    cudaEventRecord(evA, s2);

    // ---- chain B pipelined in row halves:
    //      gatherU-h1 (main) -> u1-h1 (main, overlaps gatherU-h2 on s3) -> u1-h2 -> U2
    cudaStreamWaitEvent(0, evJ, 0);
    gather_128<<<GWUH, 256>>>((const float4*)p1, off_u, csr_u, (float4*)mu, NUH);

    cudaStreamWaitEvent(s3, evJ, 0);
    cudaStreamWaitEvent(s3, evP1, 0);
    gather_128<<<GWUH, 256, 0, s3>>>((const float4*)p1, off_u + NUH, csr_u,
                                     (float4*)(mu + (size_t)NUH * HD), NU - NUH);
    cudaEventRecord(evG2, s3);

    gemm_wmma<128, false, true, true, true, false><<<296, 256, S_W128>>>(
        hu, nullptr, wbh + WB_C1RUWR, wbl + WB_C1RUWR, c1_ru_bl, mu, u1, NUH);
    cudaStreamWaitEvent(0, evG2, 0);
    gemm_wmma<128, false, true, true, true, false><<<296, 256, S_W128>>>(
        hu + (size_t)NUH * HD, nullptr, wbh + WB_C1RUWR, wbl + WB_C1RUWR, c1_ru_bl,
        mu + (size_t)NUH * HD, u1 + (size_t)NUH * HD, NU - NUH);
    gemm_wmma<128, false, false, false, false, true><<<296, 256, S_W128>>>(
        u1, nullptr, wbh + WB_U2, wbl + WB_U2, nullptr, nullptr, mu, NU);

    // ---- join; fused conv2 gather (normalized outputs) ----
    cudaStreamWaitEvent(0, evA, 0);
    gather2_64f<<<GW2, 256>>>((const float2*)mu, (const float2*)mr,
                              c2_ur_bl, c2_ru_bl,
                              off_r, csr_r, off_u, csr_u,
                              (float2*)zr, (float2*)zu);

    // ---- decoder ----
    decode_kernel<<<(NL * 32 + 255) / 256, 256>>>(
        (const float2*)zu, (const float2*)zr, lbl_src, lbl_dst, out, NL);
}

// round 15
// speedup vs baseline: 1.0545x; 1.0545x over previous
#include <cuda_runtime.h>
#include <cuda_bf16.h>
#include <mma.h>
#include <math.h>

using namespace nvcuda;

#define NU 100000
#define NR 50000
#define NE 600000
#define NL 200000
#define HD 128
#define OD 64

// ---------------- scratch (direct-store targets padded to tile multiple) ----------------
__device__ __align__(16) float g_hu[(size_t)NU * HD];
__device__ __align__(16) float g_hr[(size_t)NR * HD];
__device__ __align__(16) float g_p1[(size_t)(NR + 64) * HD];
__device__ __align__(16) float g_u1[(size_t)NU * HD];
__device__ __align__(16) float g_r1[(size_t)NR * HD];
__device__ __align__(16) float g_mean_u[(size_t)(NU + 64) * HD]; // mu, then U2
__device__ __align__(16) float g_mean_r[(size_t)(NR + 64) * HD]; // mr, then R2
__device__ __align__(16) float g_zu[(size_t)NU * OD];
__device__ __align__(16) float g_zr[(size_t)NR * OD];

// bf16 split weights, padded row pitches per matrix
__device__ __align__(16) __nv_bfloat16 g_wbh[154624];
__device__ __align__(16) __nv_bfloat16 g_wbl[154624];
#define WB_WU      0        // Wu        [128][136]
#define WB_WREC    17408    // Wrec      [128][264]
#define WB_P1      51200    // c1_ru_Wl  [128][136]
#define WB_C1UR    68608    // [c1_ur_Wl | c1_ur_Wr] stacked-K [128][264]
#define WB_C1RUWR  102400   // c1_ru_Wr  [128][136]
#define WB_U2      119808   // rows 0-63 c2_ur_Wl, 64-127 c2_ru_Wr  [128][136]
#define WB_R2      137216   // rows 0-63 c2_ru_Wl, 64-127 c2_ur_Wr  [128][136]

__device__ int g_deg_r[NR];
__device__ int g_deg_u[NU];
__device__ int g_off_r[NR + 1];
__device__ int g_off_u[NU + 1];
__device__ int g_cur_r[NR];
__device__ int g_cur_u[NU];
__device__ int g_csr_r[NE];
__device__ int g_csr_u[NE];

// ---------------- CSR build ----------------
__global__ void zero_deg(int* __restrict__ deg_u, int* __restrict__ deg_r)
{
    int t = blockIdx.x * blockDim.x + threadIdx.x;
    if (t < NU) deg_u[t] = 0;
    if (t < NR) deg_r[t] = 0;
}

__global__ void count_kernel(const int* __restrict__ es, const int* __restrict__ ed,
                             int* __restrict__ deg_u, int* __restrict__ deg_r, int E)
{
    int t = blockIdx.x * blockDim.x + threadIdx.x;
    if (t < E) {
        atomicAdd(&deg_u[es[t]], 1);
        atomicAdd(&deg_r[ed[t]], 1);
    }
}

__global__ void scan2_kernel(const int* __restrict__ deg_r, int* __restrict__ off_r,
                             int* __restrict__ cur_r,
                             const int* __restrict__ deg_u, int* __restrict__ off_u,
                             int* __restrict__ cur_u)
{
    const int* deg; int* off; int* cur; int n;
    if (blockIdx.x == 0) { deg = deg_r; off = off_r; cur = cur_r; n = NR; }
    else                 { deg = deg_u; off = off_u; cur = cur_u; n = NU; }
    __shared__ int tmp[1024];
    int t = threadIdx.x;
    int chunk = (n + 1023) / 1024;
    int start = min(t * chunk, n);
    int end = min(start + chunk, n);
    int s = 0;
    for (int i = start; i < end; i++) s += deg[i];
    tmp[t] = s;
    __syncthreads();
    for (int d = 1; d < 1024; d <<= 1) {
        int v = (t >= d) ? tmp[t - d] : 0;
        __syncthreads();
        tmp[t] += v;
        __syncthreads();
    }
    int run = (t == 0) ? 0 : tmp[t - 1];
    for (int i = start; i < end; i++) {
        off[i] = run;
        cur[i] = run;
        run += deg[i];
    }
    if (end == n) off[n] = run;
}

__global__ void fill_kernel(const int* __restrict__ es, const int* __restrict__ ed,
                            int* __restrict__ cur_u, int* __restrict__ cur_r,
                            int* __restrict__ csr_u, int* __restrict__ csr_r, int E)
{
    int t = blockIdx.x * blockDim.x + threadIdx.x;
    if (t < E) {
        int s = es[t], d = ed[t];
        int pr = atomicAdd(&cur_r[d], 1);
        csr_r[pr] = s;
        int pu = atomicAdd(&cur_u[s], 1);
        csr_u[pu] = d;
    }
}

// ---------------- bf16 split weight prep ----------------
struct WcArgs {
    const float* src[10];
    int nrows[10];
    int kcols[10];
    int cover[10];
    int pitch[10];
    int base[10];
    int blk_off[11];
};

__global__ void wconv_kernel(WcArgs a, __nv_bfloat16* __restrict__ hi,
                             __nv_bfloat16* __restrict__ lo)
{
    int b = blockIdx.x;
    int m = 0;
    while (b >= a.blk_off[m + 1]) m++;
    int idx = (b - a.blk_off[m]) * 256 + threadIdx.x;
    int NR_ = a.nrows[m], KC = a.kcols[m], CV = a.cover[m];
    if (idx < NR_ * CV) {
        int r = idx / CV, c = idx - r * CV;
        float v = (c < KC) ? a.src[m][r * KC + c] : 0.f;
        __nv_bfloat16 h = __float2bfloat16(v);
        float rr = v - __bfloat162float(h);
        int d = a.base[m] + r * a.pitch[m] + c;
        hi[d] = h;
        lo[d] = __float2bfloat16(rr);
    }
}

// ---------------- wmma split-bf16 GEMM ----------------
// DIRECT: no epilogue — store accumulators straight to gmem (Y padded to 64-row mult).
template <int K, bool DUAL, bool ADDIN, bool HASB, bool RELU, bool DIRECT>
__global__ __launch_bounds__(256) void gemm_wmma(
    const float* __restrict__ A, const float* __restrict__ X,
    const __nv_bfloat16* __restrict__ Whi, const __nv_bfloat16* __restrict__ Wlo,
    const float* __restrict__ bl, const float* __restrict__ ADDP,
    float* __restrict__ Y, int M)
{
    constexpr int KP = K + 8;
    constexpr int QR = K / 4;
    extern __shared__ __nv_bfloat16 smemb[];
    __nv_bfloat16* sWhi = smemb;
    __nv_bfloat16* sWlo = sWhi + 128 * KP;
    __nv_bfloat16* sAhi = sWlo + 128 * KP;
    __nv_bfloat16* sAlo = sAhi + 64 * KP;
    float* sOut = (float*)sAhi;

    const int tid = threadIdx.x;

    {
        const uint4* src = (const uint4*)Whi;
        uint4* dst = (uint4*)sWhi;
        for (int i = tid; i < 128 * KP / 8; i += 256) dst[i] = src[i];
        const uint4* src2 = (const uint4*)Wlo;
        uint4* dst2 = (uint4*)sWlo;
        for (int i = tid; i < 128 * KP / 8; i += 256) dst2[i] = src2[i];
    }

    const int w = tid >> 5;
    const int mrow0 = (w >> 2) * 32;
    const int ncol0 = (w & 3) * 32;

    const int ntiles = (M + 63) >> 6;
    for (int tile = blockIdx.x; tile < ntiles; tile += gridDim.x) {
        const int row0 = tile << 6;
        __syncthreads();
        {
            int rows = min(64, M - row0);
            for (int i = tid; i < 64 * QR; i += 256) {
                int r = i / QR, q = i - r * QR;
                float4 v = make_float4(0.f, 0.f, 0.f, 0.f);
                if (r < rows) {
                    if (DUAL) {
                        v = (q < 32)
                          ? *(const float4*)(A + (size_t)(row0 + r) * 128 + 4 * q)
                          : *(const float4*)(X + (size_t)(row0 + r) * 128 + 4 * (q - 32));
                    } else {
                        v = *(const float4*)(A + (size_t)(row0 + r) * K + 4 * q);
                    }
                }
                float vv[4] = {v.x, v.y, v.z, v.w};
                unsigned ph0 = 0, ph1 = 0, pl0 = 0, pl1 = 0;
#pragma unroll
                for (int qq = 0; qq < 2; qq++) {
                    __nv_bfloat16 h = __float2bfloat16(vv[qq]);
                    __nv_bfloat16 l = __float2bfloat16(vv[qq] - __bfloat162float(h));
                    ph0 |= (unsigned)__bfloat16_as_ushort(h) << (16 * qq);
                    pl0 |= (unsigned)__bfloat16_as_ushort(l) << (16 * qq);
                }
#pragma unroll
                for (int qq = 0; qq < 2; qq++) {
                    __nv_bfloat16 h = __float2bfloat16(vv[2 + qq]);
                    __nv_bfloat16 l = __float2bfloat16(vv[2 + qq] - __bfloat162float(h));
                    ph1 |= (unsigned)__bfloat16_as_ushort(h) << (16 * qq);
                    pl1 |= (unsigned)__bfloat16_as_ushort(l) << (16 * qq);
                }
                *(uint2*)&sAhi[r * KP + 4 * q] = make_uint2(ph0, ph1);
                *(uint2*)&sAlo[r * KP + 4 * q] = make_uint2(pl0, pl1);
            }
        }
        __syncthreads();

        wmma::fragment<wmma::accumulator, 16, 16, 16, float> acc[2][2];
#pragma unroll
        for (int i = 0; i < 2; i++)
#pragma unroll
            for (int j = 0; j < 2; j++) wmma::fill_fragment(acc[i][j], 0.f);

        for (int k0 = 0; k0 < K; k0 += 16) {
            wmma::fragment<wmma::matrix_a, 16, 16, 16, __nv_bfloat16, wmma::row_major> ahi[2], alo[2];
            wmma::fragment<wmma::matrix_b, 16, 16, 16, __nv_bfloat16, wmma::col_major> bhi[2], blo[2];
#pragma unroll
            for (int i = 0; i < 2; i++) {
                wmma::load_matrix_sync(ahi[i], sAhi + (mrow0 + 16 * i) * KP + k0, KP);
                wmma::load_matrix_sync(alo[i], sAlo + (mrow0 + 16 * i) * KP + k0, KP);
            }
#pragma unroll
            for (int j = 0; j < 2; j++) {
                wmma::load_matrix_sync(bhi[j], sWhi + (ncol0 + 16 * j) * KP + k0, KP);
                wmma::load_matrix_sync(blo[j], sWlo + (ncol0 + 16 * j) * KP + k0, KP);
            }
#pragma unroll
            for (int i = 0; i < 2; i++)
#pragma unroll
                for (int j = 0; j < 2; j++) {
                    wmma::mma_sync(acc[i][j], ahi[i], bhi[j], acc[i][j]);
                    wmma::mma_sync(acc[i][j], ahi[i], blo[j], acc[i][j]);
                    wmma::mma_sync(acc[i][j], alo[i], bhi[j], acc[i][j]);
                }
        }

        if (DIRECT) {
#pragma unroll
            for (int i = 0; i < 2; i++)
#pragma unroll
                for (int j = 0; j < 2; j++)
                    wmma::store_matrix_sync(
                        Y + (size_t)(row0 + mrow0 + 16 * i) * 128 + ncol0 + 16 * j,
                        acc[i][j], 128, wmma::mem_row_major);
        } else {
            __syncthreads();
#pragma unroll
            for (int i = 0; i < 2; i++)
#pragma unroll
                for (int j = 0; j < 2; j++)
                    wmma::store_matrix_sync(sOut + (mrow0 + 16 * i) * 128 + ncol0 + 16 * j,
                                            acc[i][j], 128, wmma::mem_row_major);
            __syncthreads();

            int rows = min(64, M - row0);
            for (int i = tid; i < 64 * 32; i += 256) {
                int r = i >> 5, c4 = i & 31;
                if (r < rows) {
                    float4 v = ((const float4*)sOut)[i];
                    if (HASB) {
                        float4 b4 = *(const float4*)(bl + 4 * c4);
                        v.x += b4.x; v.y += b4.y; v.z += b4.z; v.w += b4.w;
                    }
                    if (ADDIN) {
                        float4 a4 = *(const float4*)(ADDP + (size_t)(row0 + r) * 128 + 4 * c4);
                        v.x += a4.x; v.y += a4.y; v.z += a4.z; v.w += a4.w;
                    }
                    if (RELU) {
                        v.x = fmaxf(v.x, 0.f); v.y = fmaxf(v.y, 0.f);
                        v.z = fmaxf(v.z, 0.f); v.w = fmaxf(v.w, 0.f);
                    }
                    *(float4*)(Y + (size_t)(row0 + r) * 128 + 4 * c4) = v;
                }
            }
        }
    }
}

// ---------------- single-direction gather-mean 128-dim ----------------
__global__ __launch_bounds__(256) void gather_128(
    const float4* __restrict__ feat, const int* __restrict__ off,
    const int* __restrict__ csr, float4* __restrict__ outm, int n)
{
    int warp = (blockIdx.x * blockDim.x + threadIdx.x) >> 5;
    int lane = threadIdx.x & 31;
    if (warp >= n) return;
    int b = off[warp], e = off[warp + 1];
    float4 acc = make_float4(0.f, 0.f, 0.f, 0.f);
    int i = b;
    for (; i + 4 <= e; i += 4) {
        int n0 = csr[i], n1 = csr[i + 1], n2 = csr[i + 2], n3 = csr[i + 3];
        float4 v0 = feat[(size_t)n0 * 32 + lane];
        float4 v1 = feat[(size_t)n1 * 32 + lane];
        float4 v2 = feat[(size_t)n2 * 32 + lane];
        float4 v3 = feat[(size_t)n3 * 32 + lane];
        acc.x += v0.x + v1.x + v2.x + v3.x;
        acc.y += v0.y + v1.y + v2.y + v3.y;
        acc.z += v0.z + v1.z + v2.z + v3.z;
        acc.w += v0.w + v1.w + v2.w + v3.w;
    }
    for (; i < e; i++) {
        int nb = csr[i];
        float4 v = feat[(size_t)nb * 32 + lane];
        acc.x += v.x; acc.y += v.y; acc.z += v.z; acc.w += v.w;
    }
    float inv = 1.f / fmaxf((float)(e - b), 1.f);
    acc.x *= inv; acc.y *= inv; acc.z *= inv; acc.w *= inv;
    outm[(size_t)warp * 32 + lane] = acc;
}

// ---------------- 64-dim mean-only gather (cols 0..63 of 128-wide feat rows) ----------------
__global__ __launch_bounds__(256) void gather_64m(
    const float2* __restrict__ feat, const int* __restrict__ off,
    const int* __restrict__ csr, float2* __restrict__ outm, int n)
{
    int warp = (blockIdx.x * blockDim.x + threadIdx.x) >> 5;
    int lane = threadIdx.x & 31;
    if (warp >= n) return;
    int b = off[warp], e = off[warp + 1];
    float2 acc = make_float2(0.f, 0.f);
    int i = b;
    for (; i + 4 <= e; i += 4) {
        int n0 = csr[i], n1 = csr[i + 1], n2 = csr[i + 2], n3 = csr[i + 3];
        float2 v0 = feat[(size_t)n0 * 64 + lane];
        float2 v1 = feat[(size_t)n1 * 64 + lane];
        float2 v2 = feat[(size_t)n2 * 64 + lane];
        float2 v3 = feat[(size_t)n3 * 64 + lane];
        acc.x += v0.x + v1.x + v2.x + v3.x;
        acc.y += v0.y + v1.y + v2.y + v3.y;
    }
    for (; i < e; i++) {
        int nb = csr[i];
        float2 v = feat[(size_t)nb * 64 + lane];
        acc.x += v.x; acc.y += v.y;
    }
    float inv = 1.f / fmaxf((float)(e - b), 1.f);
    acc.x *= inv; acc.y *= inv;
    outm[(size_t)warp * 32 + lane] = acc;
}

// ---------------- finalize: z = normalize(mean + bl + self) (in-place) ----------------
__global__ __launch_bounds__(256) void finalize_kernel(
    const float2* __restrict__ U2, const float2* __restrict__ R2,
    const float* __restrict__ bl_ur, const float* __restrict__ bl_ru,
    float2* __restrict__ zr, float2* __restrict__ zu)
{
    int warp = (blockIdx.x * blockDim.x + threadIdx.x) >> 5;
    int lane = threadIdx.x & 31;
    const float2* selfp;
    const float2* bl;
    float2* outp;
    int node;
    if (warp < NR) {
        node = warp;
        selfp = R2; bl = (const float2*)bl_ur; outp = zr;
    } else if (warp < NR + NU) {
        node = warp - NR;
        selfp = U2; bl = (const float2*)bl_ru; outp = zu;
    } else return;
    float2 acc = outp[(size_t)node * 32 + lane];
    float2 s = selfp[(size_t)node * 64 + 32 + lane];
    float2 bb = bl[lane];
    float2 o;
    o.x = acc.x + bb.x + s.x;
    o.y = acc.y + bb.y + s.y;
    float nsum = o.x * o.x + o.y * o.y;
#pragma unroll
    for (int ofs = 16; ofs; ofs >>= 1)
        nsum += __shfl_xor_sync(0xffffffffu, nsum, ofs);
    float innorm = 1.f / fmaxf(sqrtf(nsum), 1e-12f);
    o.x *= innorm; o.y *= innorm;
    outp[(size_t)node * 32 + lane] = o;
}

// ---------------- decoder: dot of pre-normalized rows ----------------
__global__ __launch_bounds__(256) void decode_kernel(
    const float2* __restrict__ zu, const float2* __restrict__ zr,
    const int* __restrict__ ls, const int* __restrict__ ld,
    float* __restrict__ out, int L)
{
    int warp = (blockIdx.x * blockDim.x + threadIdx.x) >> 5;
    int lane = threadIdx.x & 31;
    if (warp >= L) return;
    int s = ls[warp], d = ld[warp];
    float2 a = zu[(size_t)s * 32 + lane];
    float2 b = zr[(size_t)d * 32 + lane];
    float dot = a.x * b.x + a.y * b.y;
#pragma unroll
    for (int o = 16; o; o >>= 1)
        dot += __shfl_xor_sync(0xffffffffu, dot, o);
    if (lane == 0)
        out[warp] = dot;
}

// ---------------- host launch ----------------
extern "C" void kernel_launch(void* const* d_in, const int* in_sizes, int n_in,
                              void* d_out, int out_size)
{
    const float* x_user   = (const float*)d_in[0];
    const float* x_recipe = (const float*)d_in[1];
    const int* edge_src   = (const int*)d_in[2];
    const int* edge_dst   = (const int*)d_in[3];
    const int* lbl_src    = (const int*)d_in[4];
    const int* lbl_dst    = (const int*)d_in[5];
    const float* Wu   = (const float*)d_in[6];
    const float* bu   = (const float*)d_in[7];
    const float* Wrec = (const float*)d_in[8];
    const float* brec = (const float*)d_in[9];
    const float* c1_ur_Wl = (const float*)d_in[10];
    const float* c1_ur_bl = (const float*)d_in[11];
    const float* c1_ur_Wr = (const float*)d_in[12];
    const float* c1_ru_Wl = (const float*)d_in[13];
    const float* c1_ru_bl = (const float*)d_in[14];
    const float* c1_ru_Wr = (const float*)d_in[15];
    const float* c2_ur_Wl = (const float*)d_in[16];
    const float* c2_ur_bl = (const float*)d_in[17];
    const float* c2_ur_Wr = (const float*)d_in[18];
    const float* c2_ru_Wl = (const float*)d_in[19];
    const float* c2_ru_bl = (const float*)d_in[20];
    const float* c2_ru_Wr = (const float*)d_in[21];
    float* out = (float*)d_out;

    float *hu, *hr, *p1, *u1, *r1, *mu, *mr, *zu, *zr;
    __nv_bfloat16 *wbh, *wbl;
    int *deg_r, *deg_u, *off_r, *off_u, *cur_r, *cur_u, *csr_r, *csr_u;
    cudaGetSymbolAddress((void**)&hu, g_hu);
    cudaGetSymbolAddress((void**)&hr, g_hr);
    cudaGetSymbolAddress((void**)&p1, g_p1);
    cudaGetSymbolAddress((void**)&u1, g_u1);
    cudaGetSymbolAddress((void**)&r1, g_r1);
    cudaGetSymbolAddress((void**)&mu, g_mean_u);
    cudaGetSymbolAddress((void**)&mr, g_mean_r);
    cudaGetSymbolAddress((void**)&zu, g_zu);
    cudaGetSymbolAddress((void**)&zr, g_zr);
    cudaGetSymbolAddress((void**)&wbh, g_wbh);
    cudaGetSymbolAddress((void**)&wbl, g_wbl);
    cudaGetSymbolAddress((void**)&deg_r, g_deg_r);
    cudaGetSymbolAddress((void**)&deg_u, g_deg_u);
    cudaGetSymbolAddress((void**)&off_r, g_off_r);
    cudaGetSymbolAddress((void**)&off_u, g_off_u);
    cudaGetSymbolAddress((void**)&cur_r, g_cur_r);
    cudaGetSymbolAddress((void**)&cur_u, g_cur_u);
    cudaGetSymbolAddress((void**)&csr_r, g_csr_r);
    cudaGetSymbolAddress((void**)&csr_u, g_csr_u);

    static cudaStream_t side = nullptr, s2 = nullptr;
    static cudaEvent_t evF = nullptr, evJ = nullptr, evHU = nullptr,
                       evHR = nullptr, evA = nullptr;
    if (side == nullptr) {
        cudaStreamCreateWithFlags(&side, cudaStreamNonBlocking);
        cudaStreamCreateWithFlags(&s2, cudaStreamNonBlocking);
        cudaEventCreateWithFlags(&evF, cudaEventDisableTiming);
        cudaEventCreateWithFlags(&evJ, cudaEventDisableTiming);
        cudaEventCreateWithFlags(&evHU, cudaEventDisableTiming);
        cudaEventCreateWithFlags(&evHR, cudaEventDisableTiming);
        cudaEventCreateWithFlags(&evA, cudaEventDisableTiming);
    }

    const int S_W128 = (2 * 128 * 136 + 2 * 64 * 136) * 2;   // 104448
    const int S_W256 = (2 * 128 * 264 + 2 * 64 * 264) * 2;   // 202752

    cudaFuncSetAttribute((gemm_wmma<128, false, false, true,  false, false>),
                         cudaFuncAttributeMaxDynamicSharedMemorySize, S_W128);
    cudaFuncSetAttribute((gemm_wmma<256, false, false, true,  false, false>),
                         cudaFuncAttributeMaxDynamicSharedMemorySize, S_W256);
    cudaFuncSetAttribute((gemm_wmma<128, false, false, false, false, true>),
                         cudaFuncAttributeMaxDynamicSharedMemorySize, S_W128);
    cudaFuncSetAttribute((gemm_wmma<256, true,  false, true,  true,  false>),
                         cudaFuncAttributeMaxDynamicSharedMemorySize, S_W256);
    cudaFuncSetAttribute((gemm_wmma<128, false, true,  true,  true,  false>),
                         cudaFuncAttributeMaxDynamicSharedMemorySize, S_W128);

    // ---- fork: CSR on side stream ----
    cudaEventRecord(evF, 0);
    cudaStreamWaitEvent(side, evF, 0);
    zero_deg<<<(NU + 255) / 256, 256, 0, side>>>(deg_u, deg_r);
    count_kernel<<<(NE + 255) / 256, 256, 0, side>>>(edge_src, edge_dst, deg_u, deg_r, NE);
    scan2_kernel<<<2, 1024, 0, side>>>(deg_r, off_r, cur_r, deg_u, off_u, cur_u);
    fill_kernel<<<(NE + 255) / 256, 256, 0, side>>>(edge_src, edge_dst, cur_u, cur_r,
                                                    csr_u, csr_r, NE);
    cudaEventRecord(evJ, side);

    // ---- main: bf16 split weight prep ----
    {
        WcArgs a;
        const float* srcs[10] = {Wu, Wrec, c1_ru_Wl,
                                 c1_ur_Wl, c1_ur_Wr,
                                 c1_ru_Wr,
                                 c2_ur_Wl, c2_ru_Wr,
                                 c2_ru_Wl, c2_ur_Wr};
        int nr[10] = {128, 128, 128, 128, 128, 128, 64, 64, 64, 64};
        int kc[10] = {128, 256, 128, 128, 128, 128, 128, 128, 128, 128};
        int cv[10] = {136, 264, 136, 128, 136, 136, 136, 136, 136, 136};
        int pt[10] = {136, 264, 136, 264, 264, 136, 136, 136, 136, 136};
        int bs[10] = {WB_WU, WB_WREC, WB_P1,
                      WB_C1UR, WB_C1UR + 128,
                      WB_C1RUWR,
                      WB_U2, WB_U2 + 64 * 136,
                      WB_R2, WB_R2 + 64 * 136};
        int boff = 0;
        for (int m = 0; m < 10; m++) {
            a.src[m] = srcs[m]; a.nrows[m] = nr[m]; a.kcols[m] = kc[m];
            a.cover[m] = cv[m]; a.pitch[m] = pt[m]; a.base[m] = bs[m];
            a.blk_off[m] = boff;
            boff += (nr[m] * cv[m] + 255) / 256;
        }
        a.blk_off[10] = boff;
        wconv_kernel<<<boff, 256>>>(a, wbh, wbl);
    }

    const int GWR = (NR * 32 + 255) / 256;
    const int GWU = (NU * 32 + 255) / 256;
    const int GW2 = ((NR + NU) * 32 + 255) / 256;

    // ---- main: hu projection; then hr -> p1 ----
    gemm_wmma<128, false, false, true, false, false><<<296, 256, S_W128>>>(
        x_user, nullptr, wbh + WB_WU, wbl + WB_WU, bu, nullptr, hu, NU);
    cudaEventRecord(evHU, 0);

    // ---- s2: gatherR (mr from hu) overlaps hr/p1 GEMMs on main ----
    cudaStreamWaitEvent(s2, evJ, 0);
    cudaStreamWaitEvent(s2, evHU, 0);
    gather_128<<<GWR, 256, 0, s2>>>((const float4*)hu, off_r, csr_r, (float4*)mr, NR);

    gemm_wmma<256, false, false, true, false, false><<<148, 256, S_W256>>>(
        x_recipe, nullptr, wbh + WB_WREC, wbl + WB_WREC, brec, nullptr, hr, NR);
    cudaEventRecord(evHR, 0);
    gemm_wmma<128, false, false, false, false, true><<<296, 256, S_W128>>>(
        hr, nullptr, wbh + WB_P1, wbl + WB_P1, nullptr, nullptr, p1, NR);

    // ---- s2: chain A: r1 (stacked dual) -> R2 -> zu-mean gather ----
    cudaStreamWaitEvent(s2, evHR, 0);
    gemm_wmma<256, true, false, true, true, false><<<148, 256, S_W256, s2>>>(
        mr, hr, wbh + WB_C1UR, wbl + WB_C1UR, c1_ur_bl, nullptr, r1, NR);
    gemm_wmma<128, false, false, false, false, true><<<296, 256, S_W128, s2>>>(
        r1, nullptr, wbh + WB_R2, wbl + WB_R2, nullptr, nullptr, mr, NR);
    // zu-mean: users gather R2 (= mr) over csr_u; overlaps u1/U2 on main
    gather_64m<<<GWU, 256, 0, s2>>>((const float2*)mr, off_u, csr_u, (float2*)zu, NU);
    cudaEventRecord(evA, s2);

    // ---- main: gatherU (mu from p1); chain B: u1 -> U2 -> zr-mean gather ----
    cudaStreamWaitEvent(0, evJ, 0);
    gather_128<<<GWU, 256>>>((const float4*)p1, off_u, csr_u, (float4*)mu, NU);
    gemm_wmma<128, false, true, true, true, false><<<296, 256, S_W128>>>(
        hu, nullptr, wbh + WB_C1RUWR, wbl + WB_C1RUWR, c1_ru_bl, mu, u1, NU);
    gemm_wmma<128, false, false, false, false, true><<<296, 256, S_W128>>>(
        u1, nullptr, wbh + WB_U2, wbl + WB_U2, nullptr, nullptr, mu, NU);
    // zr-mean: recipes gather U2 (= mu) over csr_r
    gather_64m<<<GWR, 256>>>((const float2*)mu, off_r, csr_r, (float2*)zr, NR);

    // ---- join; finalize (bias + self + normalize, in-place) ----
    cudaStreamWaitEvent(0, evA, 0);
    finalize_kernel<<<GW2, 256>>>((const float2*)mu, (const float2*)mr,
                                  c2_ur_bl, c2_ru_bl,
                                  (float2*)zr, (float2*)zu);

    // ---- decoder ----
    decode_kernel<<<(NL * 32 + 255) / 256, 256>>>(
        (const float2*)zu, (const float2*)zr, lbl_src, lbl_dst, out, NL);
}

// round 16
// speedup vs baseline: 1.0586x; 1.0040x over previous
#include <cuda_runtime.h>
#include <cuda_bf16.h>
#include <mma.h>
#include <math.h>

using namespace nvcuda;

#define NU 100000
#define NR 50000
#define NE 600000
#define NL 200000
#define HD 128
#define OD 64

// ---------------- scratch (direct-store targets padded to tile multiple) ----------------
__device__ __align__(16) float g_hu[(size_t)NU * HD];
__device__ __align__(16) float g_hr[(size_t)NR * HD];
__device__ __align__(16) float g_p1[(size_t)(NR + 64) * HD];
__device__ __align__(16) float g_u1[(size_t)(NU + 64) * HD];   // t = hu@Wr (raw)
__device__ __align__(16) float g_r1[(size_t)(NR + 64) * HD];   // r1s = mr@Wl+hr@Wr (raw)
__device__ __align__(16) float g_mean_u[(size_t)(NU + 64) * HD]; // mu, then U2
__device__ __align__(16) float g_mean_r[(size_t)(NR + 64) * HD]; // mr, then R2
__device__ __align__(16) float g_zu[(size_t)NU * OD];
__device__ __align__(16) float g_zr[(size_t)NR * OD];

// bf16 split weights, padded row pitches per matrix
__device__ __align__(16) __nv_bfloat16 g_wbh[154624];
__device__ __align__(16) __nv_bfloat16 g_wbl[154624];
#define WB_WU      0        // Wu        [128][136]
#define WB_WREC    17408    // Wrec      [128][264]
#define WB_P1      51200    // c1_ru_Wl  [128][136]
#define WB_C1UR    68608    // [c1_ur_Wl | c1_ur_Wr] stacked-K [128][264]
#define WB_C1RUWR  102400   // c1_ru_Wr  [128][136]
#define WB_U2      119808   // rows 0-63 c2_ur_Wl, 64-127 c2_ru_Wr  [128][136]
#define WB_R2      137216   // rows 0-63 c2_ru_Wl, 64-127 c2_ur_Wr  [128][136]

__device__ int g_deg_r[NR];
__device__ int g_deg_u[NU];
__device__ int g_off_r[NR + 1];
__device__ int g_off_u[NU + 1];
__device__ int g_cur_r[NR];
__device__ int g_cur_u[NU];
__device__ int g_csr_r[NE];
__device__ int g_csr_u[NE];

// ---------------- CSR build ----------------
__global__ void zero_deg(int* __restrict__ deg_u, int* __restrict__ deg_r)
{
    int t = blockIdx.x * blockDim.x + threadIdx.x;
    if (t < NU) deg_u[t] = 0;
    if (t < NR) deg_r[t] = 0;
}

__global__ void count_kernel(const int* __restrict__ es, const int* __restrict__ ed,
                             int* __restrict__ deg_u, int* __restrict__ deg_r, int E)
{
    int t = blockIdx.x * blockDim.x + threadIdx.x;
    if (t < E) {
        atomicAdd(&deg_u[es[t]], 1);
        atomicAdd(&deg_r[ed[t]], 1);
    }
}

__global__ void scan2_kernel(const int* __restrict__ deg_r, int* __restrict__ off_r,
                             int* __restrict__ cur_r,
                             const int* __restrict__ deg_u, int* __restrict__ off_u,
                             int* __restrict__ cur_u)
{
    const int* deg; int* off; int* cur; int n;
    if (blockIdx.x == 0) { deg = deg_r; off = off_r; cur = cur_r; n = NR; }
    else                 { deg = deg_u; off = off_u; cur = cur_u; n = NU; }
    __shared__ int tmp[1024];
    int t = threadIdx.x;
    int chunk = (n + 1023) / 1024;
    int start = min(t * chunk, n);
    int end = min(start + chunk, n);
    int s = 0;
    for (int i = start; i < end; i++) s += deg[i];
    tmp[t] = s;
    __syncthreads();
    for (int d = 1; d < 1024; d <<= 1) {
        int v = (t >= d) ? tmp[t - d] : 0;
        __syncthreads();
        tmp[t] += v;
        __syncthreads();
    }
    int run = (t == 0) ? 0 : tmp[t - 1];
    for (int i = start; i < end; i++) {
        off[i] = run;
        cur[i] = run;
        run += deg[i];
    }
    if (end == n) off[n] = run;
}

__global__ void fill_kernel(const int* __restrict__ es, const int* __restrict__ ed,
                            int* __restrict__ cur_u, int* __restrict__ cur_r,
                            int* __restrict__ csr_u, int* __restrict__ csr_r, int E)
{
    int t = blockIdx.x * blockDim.x + threadIdx.x;
    if (t < E) {
        int s = es[t], d = ed[t];
        int pr = atomicAdd(&cur_r[d], 1);
        csr_r[pr] = s;
        int pu = atomicAdd(&cur_u[s], 1);
        csr_u[pu] = d;
    }
}

// ---------------- bf16 split weight prep ----------------
struct WcArgs {
    const float* src[10];
    int nrows[10];
    int kcols[10];
    int cover[10];
    int pitch[10];
    int base[10];
    int blk_off[11];
};

__global__ void wconv_kernel(WcArgs a, __nv_bfloat16* __restrict__ hi,
                             __nv_bfloat16* __restrict__ lo)
{
    int b = blockIdx.x;
    int m = 0;
    while (b >= a.blk_off[m + 1]) m++;
    int idx = (b - a.blk_off[m]) * 256 + threadIdx.x;
    int NR_ = a.nrows[m], KC = a.kcols[m], CV = a.cover[m];
    if (idx < NR_ * CV) {
        int r = idx / CV, c = idx - r * CV;
        float v = (c < KC) ? a.src[m][r * KC + c] : 0.f;
        __nv_bfloat16 h = __float2bfloat16(v);
        float rr = v - __bfloat162float(h);
        int d = a.base[m] + r * a.pitch[m] + c;
        hi[d] = h;
        lo[d] = __float2bfloat16(rr);
    }
}

// ---------------- wmma split-bf16 GEMM ----------------
// DIRECT: store accumulators straight to gmem (Y padded to 64-row mult).
// SF: staging computes A' = relu(A + bl[k] (+ADDP[row][k] if SADD)) before split
//     (K=128, !DUAL only; bl/ADDP are reused as staging-side operands).
template <int K, bool DUAL, bool ADDIN, bool HASB, bool RELU, bool DIRECT,
          bool SF, bool SADD>
__global__ __launch_bounds__(256) void gemm_wmma(
    const float* __restrict__ A, const float* __restrict__ X,
    const __nv_bfloat16* __restrict__ Whi, const __nv_bfloat16* __restrict__ Wlo,
    const float* __restrict__ bl, const float* __restrict__ ADDP,
    float* __restrict__ Y, int M)
{
    constexpr int KP = K + 8;
    constexpr int QR = K / 4;
    extern __shared__ __nv_bfloat16 smemb[];
    __nv_bfloat16* sWhi = smemb;
    __nv_bfloat16* sWlo = sWhi + 128 * KP;
    __nv_bfloat16* sAhi = sWlo + 128 * KP;
    __nv_bfloat16* sAlo = sAhi + 64 * KP;
    float* sOut = (float*)sAhi;

    const int tid = threadIdx.x;

    {
        const uint4* src = (const uint4*)Whi;
        uint4* dst = (uint4*)sWhi;
        for (int i = tid; i < 128 * KP / 8; i += 256) dst[i] = src[i];
        const uint4* src2 = (const uint4*)Wlo;
        uint4* dst2 = (uint4*)sWlo;
        for (int i = tid; i < 128 * KP / 8; i += 256) dst2[i] = src2[i];
    }

    const int w = tid >> 5;
    const int mrow0 = (w >> 2) * 32;
    const int ncol0 = (w & 3) * 32;

    const int ntiles = (M + 63) >> 6;
    for (int tile = blockIdx.x; tile < ntiles; tile += gridDim.x) {
        const int row0 = tile << 6;
        __syncthreads();
        {
            int rows = min(64, M - row0);
            for (int i = tid; i < 64 * QR; i += 256) {
                int r = i / QR, q = i - r * QR;
                float4 v = make_float4(0.f, 0.f, 0.f, 0.f);
                if (r < rows) {
                    if (DUAL) {
                        v = (q < 32)
                          ? *(const float4*)(A + (size_t)(row0 + r) * 128 + 4 * q)
                          : *(const float4*)(X + (size_t)(row0 + r) * 128 + 4 * (q - 32));
                    } else {
                        v = *(const float4*)(A + (size_t)(row0 + r) * K + 4 * q);
                    }
                    if (SF) {
                        float4 b4 = *(const float4*)(bl + 4 * q);
                        v.x += b4.x; v.y += b4.y; v.z += b4.z; v.w += b4.w;
                        if (SADD) {
                            float4 m4 = *(const float4*)(ADDP + (size_t)(row0 + r) * 128 + 4 * q);
                            v.x += m4.x; v.y += m4.y; v.z += m4.z; v.w += m4.w;
                        }
                        v.x = fmaxf(v.x, 0.f); v.y = fmaxf(v.y, 0.f);
                        v.z = fmaxf(v.z, 0.f); v.w = fmaxf(v.w, 0.f);
                    }
                }
                float vv[4] = {v.x, v.y, v.z, v.w};
                unsigned ph0 = 0, ph1 = 0, pl0 = 0, pl1 = 0;
#pragma unroll
                for (int qq = 0; qq < 2; qq++) {
                    __nv_bfloat16 h = __float2bfloat16(vv[qq]);
                    __nv_bfloat16 l = __float2bfloat16(vv[qq] - __bfloat162float(h));
                    ph0 |= (unsigned)__bfloat16_as_ushort(h) << (16 * qq);
                    pl0 |= (unsigned)__bfloat16_as_ushort(l) << (16 * qq);
                }
#pragma unroll
                for (int qq = 0; qq < 2; qq++) {
                    __nv_bfloat16 h = __float2bfloat16(vv[2 + qq]);
                    __nv_bfloat16 l = __float2bfloat16(vv[2 + qq] - __bfloat162float(h));
                    ph1 |= (unsigned)__bfloat16_as_ushort(h) << (16 * qq);
                    pl1 |= (unsigned)__bfloat16_as_ushort(l) << (16 * qq);
                }
                *(uint2*)&sAhi[r * KP + 4 * q] = make_uint2(ph0, ph1);
                *(uint2*)&sAlo[r * KP + 4 * q] = make_uint2(pl0, pl1);
            }
        }
        __syncthreads();

        wmma::fragment<wmma::accumulator, 16, 16, 16, float> acc[2][2];
#pragma unroll
        for (int i = 0; i < 2; i++)
#pragma unroll
            for (int j = 0; j < 2; j++) wmma::fill_fragment(acc[i][j], 0.f);

        for (int k0 = 0; k0 < K; k0 += 16) {
            wmma::fragment<wmma::matrix_a, 16, 16, 16, __nv_bfloat16, wmma::row_major> ahi[2], alo[2];
            wmma::fragment<wmma::matrix_b, 16, 16, 16, __nv_bfloat16, wmma::col_major> bhi[2], blo[2];
#pragma unroll
            for (int i = 0; i < 2; i++) {
                wmma::load_matrix_sync(ahi[i], sAhi + (mrow0 + 16 * i) * KP + k0, KP);
                wmma::load_matrix_sync(alo[i], sAlo + (mrow0 + 16 * i) * KP + k0, KP);
            }
#pragma unroll
            for (int j = 0; j < 2; j++) {
                wmma::load_matrix_sync(bhi[j], sWhi + (ncol0 + 16 * j) * KP + k0, KP);
                wmma::load_matrix_sync(blo[j], sWlo + (ncol0 + 16 * j) * KP + k0, KP);
            }
#pragma unroll
            for (int i = 0; i < 2; i++)
#pragma unroll
                for (int j = 0; j < 2; j++) {
                    wmma::mma_sync(acc[i][j], ahi[i], bhi[j], acc[i][j]);
                    wmma::mma_sync(acc[i][j], ahi[i], blo[j], acc[i][j]);
                    wmma::mma_sync(acc[i][j], alo[i], bhi[j], acc[i][j]);
                }
        }

        if (DIRECT) {
#pragma unroll
            for (int i = 0; i < 2; i++)
#pragma unroll
                for (int j = 0; j < 2; j++)
                    wmma::store_matrix_sync(
                        Y + (size_t)(row0 + mrow0 + 16 * i) * 128 + ncol0 + 16 * j,
                        acc[i][j], 128, wmma::mem_row_major);
        } else {
            __syncthreads();
#pragma unroll
            for (int i = 0; i < 2; i++)
#pragma unroll
                for (int j = 0; j < 2; j++)
                    wmma::store_matrix_sync(sOut + (mrow0 + 16 * i) * 128 + ncol0 + 16 * j,
                                            acc[i][j], 128, wmma::mem_row_major);
            __syncthreads();

            int rows = min(64, M - row0);
            for (int i = tid; i < 64 * 32; i += 256) {
                int r = i >> 5, c4 = i & 31;
                if (r < rows) {
                    float4 v = ((const float4*)sOut)[i];
                    if (HASB) {
                        float4 b4 = *(const float4*)(bl + 4 * c4);
                        v.x += b4.x; v.y += b4.y; v.z += b4.z; v.w += b4.w;
                    }
                    if (ADDIN) {
                        float4 a4 = *(const float4*)(ADDP + (size_t)(row0 + r) * 128 + 4 * c4);
                        v.x += a4.x; v.y += a4.y; v.z += a4.z; v.w += a4.w;
                    }
                    if (RELU) {
                        v.x = fmaxf(v.x, 0.f); v.y = fmaxf(v.y, 0.f);
                        v.z = fmaxf(v.z, 0.f); v.w = fmaxf(v.w, 0.f);
                    }
                    *(float4*)(Y + (size_t)(row0 + r) * 128 + 4 * c4) = v;
                }
            }
        }
    }
}

// ---------------- single-direction gather-mean 128-dim ----------------
__global__ __launch_bounds__(256) void gather_128(
    const float4* __restrict__ feat, const int* __restrict__ off,
    const int* __restrict__ csr, float4* __restrict__ outm, int n)
{
    int warp = (blockIdx.x * blockDim.x + threadIdx.x) >> 5;
    int lane = threadIdx.x & 31;
    if (warp >= n) return;
    int b = off[warp], e = off[warp + 1];
    float4 acc = make_float4(0.f, 0.f, 0.f, 0.f);
    int i = b;
    for (; i + 4 <= e; i += 4) {
        int n0 = csr[i], n1 = csr[i + 1], n2 = csr[i + 2], n3 = csr[i + 3];
        float4 v0 = feat[(size_t)n0 * 32 + lane];
        float4 v1 = feat[(size_t)n1 * 32 + lane];
        float4 v2 = feat[(size_t)n2 * 32 + lane];
        float4 v3 = feat[(size_t)n3 * 32 + lane];
        acc.x += v0.x + v1.x + v2.x + v3.x;
        acc.y += v0.y + v1.y + v2.y + v3.y;
        acc.z += v0.z + v1.z + v2.z + v3.z;
        acc.w += v0.w + v1.w + v2.w + v3.w;
    }
    for (; i < e; i++) {
        int nb = csr[i];
        float4 v = feat[(size_t)nb * 32 + lane];
        acc.x += v.x; acc.y += v.y; acc.z += v.z; acc.w += v.w;
    }
    float inv = 1.f / fmaxf((float)(e - b), 1.f);
    acc.x *= inv; acc.y *= inv; acc.z *= inv; acc.w *= inv;
    outm[(size_t)warp * 32 + lane] = acc;
}

// ---------------- 64-dim mean-only gather (cols 0..63 of 128-wide feat rows) ----------------
__global__ __launch_bounds__(256) void gather_64m(
    const float2* __restrict__ feat, const int* __restrict__ off,
    const int* __restrict__ csr, float2* __restrict__ outm, int n)
{
    int warp = (blockIdx.x * blockDim.x + threadIdx.x) >> 5;
    int lane = threadIdx.x & 31;
    if (warp >= n) return;
    int b = off[warp], e = off[warp + 1];
    float2 acc = make_float2(0.f, 0.f);
    int i = b;
    for (; i + 4 <= e; i += 4) {
        int n0 = csr[i], n1 = csr[i + 1], n2 = csr[i + 2], n3 = csr[i + 3];
        float2 v0 = feat[(size_t)n0 * 64 + lane];
        float2 v1 = feat[(size_t)n1 * 64 + lane];
        float2 v2 = feat[(size_t)n2 * 64 + lane];
        float2 v3 = feat[(size_t)n3 * 64 + lane];
        acc.x += v0.x + v1.x + v2.x + v3.x;
        acc.y += v0.y + v1.y + v2.y + v3.y;
    }
    for (; i < e; i++) {
        int nb = csr[i];
        float2 v = feat[(size_t)nb * 64 + lane];
        acc.x += v.x; acc.y += v.y;
    }
    float inv = 1.f / fmaxf((float)(e - b), 1.f);
    acc.x *= inv; acc.y *= inv;
    outm[(size_t)warp * 32 + lane] = acc;
}

// ---------------- finalize: z = normalize(mean + bl + self) (in-place) ----------------
__global__ __launch_bounds__(256) void finalize_kernel(
    const float2* __restrict__ U2, const float2* __restrict__ R2,
    const float* __restrict__ bl_ur, const float* __restrict__ bl_ru,
    float2* __restrict__ zr, float2* __restrict__ zu)
{
    int warp = (blockIdx.x * blockDim.x + threadIdx.x) >> 5;
    int lane = threadIdx.x & 31;
    const float2* selfp;
    const float2* bl;
    float2* outp;
    int node;
    if (warp < NR) {
        node = warp;
        selfp = R2; bl = (const float2*)bl_ur; outp = zr;
    } else if (warp < NR + NU) {
        node = warp - NR;
        selfp = U2; bl = (const float2*)bl_ru; outp = zu;
    } else return;
    float2 acc = outp[(size_t)node * 32 + lane];
    float2 s = selfp[(size_t)node * 64 + 32 + lane];
    float2 bb = bl[lane];
    float2 o;
    o.x = acc.x + bb.x + s.x;
    o.y = acc.y + bb.y + s.y;
    float nsum = o.x * o.x + o.y * o.y;
#pragma unroll
    for (int ofs = 16; ofs; ofs >>= 1)
        nsum += __shfl_xor_sync(0xffffffffu, nsum, ofs);
    float innorm = 1.f / fmaxf(sqrtf(nsum), 1e-12f);
    o.x *= innorm; o.y *= innorm;
    outp[(size_t)node * 32 + lane] = o;
}

// ---------------- decoder: dot of pre-normalized rows ----------------
__global__ __launch_bounds__(256) void decode_kernel(
    const float2* __restrict__ zu, const float2* __restrict__ zr,
    const int* __restrict__ ls, const int* __restrict__ ld,
    float* __restrict__ out, int L)
{
    int warp = (blockIdx.x * blockDim.x + threadIdx.x) >> 5;
    int lane = threadIdx.x & 31;
    if (warp >= L) return;
    int s = ls[warp], d = ld[warp];
    float2 a = zu[(size_t)s * 32 + lane];
    float2 b = zr[(size_t)d * 32 + lane];
    float dot = a.x * b.x + a.y * b.y;
#pragma unroll
    for (int o = 16; o; o >>= 1)
        dot += __shfl_xor_sync(0xffffffffu, dot, o);
    if (lane == 0)
        out[warp] = dot;
}

// ---------------- host launch ----------------
extern "C" void kernel_launch(void* const* d_in, const int* in_sizes, int n_in,
                              void* d_out, int out_size)
{
    const float* x_user   = (const float*)d_in[0];
    const float* x_recipe = (const float*)d_in[1];
    const int* edge_src   = (const int*)d_in[2];
    const int* edge_dst   = (const int*)d_in[3];
    const int* lbl_src    = (const int*)d_in[4];
    const int* lbl_dst    = (const int*)d_in[5];
    const float* Wu   = (const float*)d_in[6];
    const float* bu   = (const float*)d_in[7];
    const float* Wrec = (const float*)d_in[8];
    const float* brec = (const float*)d_in[9];
    const float* c1_ur_Wl = (const float*)d_in[10];
    const float* c1_ur_bl = (const float*)d_in[11];
    const float* c1_ur_Wr = (const float*)d_in[12];
    const float* c1_ru_Wl = (const float*)d_in[13];
    const float* c1_ru_bl = (const float*)d_in[14];
    const float* c1_ru_Wr = (const float*)d_in[15];
    const float* c2_ur_Wl = (const float*)d_in[16];
    const float* c2_ur_bl = (const float*)d_in[17];
    const float* c2_ur_Wr = (const float*)d_in[18];
    const float* c2_ru_Wl = (const float*)d_in[19];
    const float* c2_ru_bl = (const float*)d_in[20];
    const float* c2_ru_Wr = (const float*)d_in[21];
    float* out = (float*)d_out;

    float *hu, *hr, *p1, *u1, *r1, *mu, *mr, *zu, *zr;
    __nv_bfloat16 *wbh, *wbl;
    int *deg_r, *deg_u, *off_r, *off_u, *cur_r, *cur_u, *csr_r, *csr_u;
    cudaGetSymbolAddress((void**)&hu, g_hu);
    cudaGetSymbolAddress((void**)&hr, g_hr);
    cudaGetSymbolAddress((void**)&p1, g_p1);
    cudaGetSymbolAddress((void**)&u1, g_u1);
    cudaGetSymbolAddress((void**)&r1, g_r1);
    cudaGetSymbolAddress((void**)&mu, g_mean_u);
    cudaGetSymbolAddress((void**)&mr, g_mean_r);
    cudaGetSymbolAddress((void**)&zu, g_zu);
    cudaGetSymbolAddress((void**)&zr, g_zr);
    cudaGetSymbolAddress((void**)&wbh, g_wbh);
    cudaGetSymbolAddress((void**)&wbl, g_wbl);
    cudaGetSymbolAddress((void**)&deg_r, g_deg_r);
    cudaGetSymbolAddress((void**)&deg_u, g_deg_u);
    cudaGetSymbolAddress((void**)&off_r, g_off_r);
    cudaGetSymbolAddress((void**)&off_u, g_off_u);
    cudaGetSymbolAddress((void**)&cur_r, g_cur_r);
    cudaGetSymbolAddress((void**)&cur_u, g_cur_u);
    cudaGetSymbolAddress((void**)&csr_r, g_csr_r);
    cudaGetSymbolAddress((void**)&csr_u, g_csr_u);

    static cudaStream_t side = nullptr, s2 = nullptr, s3 = nullptr;
    static cudaEvent_t evF = nullptr, evJ = nullptr, evHU = nullptr,
                       evHR = nullptr, evA = nullptr, evP1 = nullptr,
                       evGU = nullptr;
    if (side == nullptr) {
        cudaStreamCreateWithFlags(&side, cudaStreamNonBlocking);
        cudaStreamCreateWithFlags(&s2, cudaStreamNonBlocking);
        cudaStreamCreateWithFlags(&s3, cudaStreamNonBlocking);
        cudaEventCreateWithFlags(&evF, cudaEventDisableTiming);
        cudaEventCreateWithFlags(&evJ, cudaEventDisableTiming);
        cudaEventCreateWithFlags(&evHU, cudaEventDisableTiming);
        cudaEventCreateWithFlags(&evHR, cudaEventDisableTiming);
        cudaEventCreateWithFlags(&evA, cudaEventDisableTiming);
        cudaEventCreateWithFlags(&evP1, cudaEventDisableTiming);
        cudaEventCreateWithFlags(&evGU, cudaEventDisableTiming);
    }

    const int S_W128 = (2 * 128 * 136 + 2 * 64 * 136) * 2;   // 104448
    const int S_W256 = (2 * 128 * 264 + 2 * 64 * 264) * 2;   // 202752

    // kernel aliases
    auto kHU  = gemm_wmma<128, false, false, true,  false, false, false, false>;
    auto kHR  = gemm_wmma<256, false, false, true,  false, false, false, false>;
    auto kDIR = gemm_wmma<128, false, false, false, false, true,  false, false>; // p1, t
    auto kR1S = gemm_wmma<256, true,  false, false, false, true,  false, false>; // r1s
    auto kR2  = gemm_wmma<128, false, false, false, false, true,  true,  false>; // R2 (SF)
    auto kU2  = gemm_wmma<128, false, false, false, false, true,  true,  true>;  // U2 (SF+SADD)

    cudaFuncSetAttribute(kHU,  cudaFuncAttributeMaxDynamicSharedMemorySize, S_W128);
    cudaFuncSetAttribute(kHR,  cudaFuncAttributeMaxDynamicSharedMemorySize, S_W256);
    cudaFuncSetAttribute(kDIR, cudaFuncAttributeMaxDynamicSharedMemorySize, S_W128);
    cudaFuncSetAttribute(kR1S, cudaFuncAttributeMaxDynamicSharedMemorySize, S_W256);
    cudaFuncSetAttribute(kR2,  cudaFuncAttributeMaxDynamicSharedMemorySize, S_W128);
    cudaFuncSetAttribute(kU2,  cudaFuncAttributeMaxDynamicSharedMemorySize, S_W128);

    // ---- fork: CSR on side stream ----
    cudaEventRecord(evF, 0);
    cudaStreamWaitEvent(side, evF, 0);
    zero_deg<<<(NU + 255) / 256, 256, 0, side>>>(deg_u, deg_r);
    count_kernel<<<(NE + 255) / 256, 256, 0, side>>>(edge_src, edge_dst, deg_u, deg_r, NE);
    scan2_kernel<<<2, 1024, 0, side>>>(deg_r, off_r, cur_r, deg_u, off_u, cur_u);
    fill_kernel<<<(NE + 255) / 256, 256, 0, side>>>(edge_src, edge_dst, cur_u, cur_r,
                                                    csr_u, csr_r, NE);
    cudaEventRecord(evJ, side);

    // ---- main: bf16 split weight prep ----
    {
        WcArgs a;
        const float* srcs[10] = {Wu, Wrec, c1_ru_Wl,
                                 c1_ur_Wl, c1_ur_Wr,
                                 c1_ru_Wr,
                                 c2_ur_Wl, c2_ru_Wr,
                                 c2_ru_Wl, c2_ur_Wr};
        int nr[10] = {128, 128, 128, 128, 128, 128, 64, 64, 64, 64};
        int kc[10] = {128, 256, 128, 128, 128, 128, 128, 128, 128, 128};
        int cv[10] = {136, 264, 136, 128, 136, 136, 136, 136, 136, 136};
        int pt[10] = {136, 264, 136, 264, 264, 136, 136, 136, 136, 136};
        int bs[10] = {WB_WU, WB_WREC, WB_P1,
                      WB_C1UR, WB_C1UR + 128,
                      WB_C1RUWR,
                      WB_U2, WB_U2 + 64 * 136,
                      WB_R2, WB_R2 + 64 * 136};
        int boff = 0;
        for (int m = 0; m < 10; m++) {
            a.src[m] = srcs[m]; a.nrows[m] = nr[m]; a.kcols[m] = kc[m];
            a.cover[m] = cv[m]; a.pitch[m] = pt[m]; a.base[m] = bs[m];
            a.blk_off[m] = boff;
            boff += (nr[m] * cv[m] + 255) / 256;
        }
        a.blk_off[10] = boff;
        wconv_kernel<<<boff, 256>>>(a, wbh, wbl);
    }

    const int GWR = (NR * 32 + 255) / 256;
    const int GWU = (NU * 32 + 255) / 256;
    const int GW2 = ((NR + NU) * 32 + 255) / 256;

    // ---- main: hu projection; then hr -> p1 ----
    kHU<<<296, 256, S_W128>>>(x_user, nullptr, wbh + WB_WU, wbl + WB_WU,
                              bu, nullptr, hu, NU);
    cudaEventRecord(evHU, 0);

    // ---- s2: gatherR (mr from hu) overlaps hr/p1 GEMMs on main ----
    cudaStreamWaitEvent(s2, evJ, 0);
    cudaStreamWaitEvent(s2, evHU, 0);
    gather_128<<<GWR, 256, 0, s2>>>((const float4*)hu, off_r, csr_r, (float4*)mr, NR);

    kHR<<<148, 256, S_W256>>>(x_recipe, nullptr, wbh + WB_WREC, wbl + WB_WREC,
                              brec, nullptr, hr, NR);
    cudaEventRecord(evHR, 0);
    kDIR<<<296, 256, S_W128>>>(hr, nullptr, wbh + WB_P1, wbl + WB_P1,
                               nullptr, nullptr, p1, NR);
    cudaEventRecord(evP1, 0);

    // ---- s2: chain A: r1s (stacked dual, DIRECT) -> R2 (SF relu+bias) -> zu-mean ----
    cudaStreamWaitEvent(s2, evHR, 0);
    kR1S<<<148, 256, S_W256, s2>>>(mr, hr, wbh + WB_C1UR, wbl + WB_C1UR,
                                   nullptr, nullptr, r1, NR);
    kR2<<<296, 256, S_W128, s2>>>(r1, nullptr, wbh + WB_R2, wbl + WB_R2,
                                  c1_ur_bl, nullptr, mr, NR);
    gather_64m<<<GWU, 256, 0, s2>>>((const float2*)mr, off_u, csr_u, (float2*)zu, NU);
    cudaEventRecord(evA, s2);

    // ---- s3: gatherU (mu from p1) overlaps t-GEMM on main ----
    cudaStreamWaitEvent(s3, evJ, 0);
    cudaStreamWaitEvent(s3, evP1, 0);
    gather_128<<<GWU, 256, 0, s3>>>((const float4*)p1, off_u, csr_u, (float4*)mu, NU);
    cudaEventRecord(evGU, s3);

    // ---- main: t = hu @ c1_ru_Wr (DIRECT); then U2 (SF: relu(t+bl+mu)) -> zr-mean ----
    kDIR<<<296, 256, S_W128>>>(hu, nullptr, wbh + WB_C1RUWR, wbl + WB_C1RUWR,
                               nullptr, nullptr, u1, NU);
    cudaStreamWaitEvent(0, evGU, 0);
    kU2<<<296, 256, S_W128>>>(u1, nullptr, wbh + WB_U2, wbl + WB_U2,
                              c1_ru_bl, mu, mu, NU);
    gather_64m<<<GWR, 256>>>((const float2*)mu, off_r, csr_r, (float2*)zr, NR);

    // ---- join; finalize (bias + self + normalize, in-place) ----
    cudaStreamWaitEvent(0, evA, 0);
    finalize_kernel<<<GW2, 256>>>((const float2*)mu, (const float2*)mr,
                                  c2_ur_bl, c2_ru_bl,
                                  (float2*)zr, (float2*)zu);

    // ---- decoder ----
    decode_kernel<<<(NL * 32 + 255) / 256, 256>>>(
        (const float2*)zu, (const float2*)zr, lbl_src, lbl_dst, out, NL);
}